// round 12
// baseline (speedup 1.0000x reference)
#include <cuda_runtime.h>
#include <cstdint>

#define BATCH 1024
#define SEQL  200
#define DIM   128

// Scratch (allocation-free rule: __device__ globals)
// Xf layout: [128 global ksteps][128 n][4 tig] float4 = {hi_k, lo_k, hi_k+4, lo_k+4}
// where k = kstep*8 + tig (k = GEMM reduction index = row of X).
__device__ float xf0_buf[128 * 128 * 16];          // g   (1 MB)
__device__ float xf1_buf[128 * 128 * 16];          // ag  (1 MB)
__device__ float part_buf[8 * BATCH * DIM];        // 8 K-split partials (4 MB)

// ---------------------------------------------------------------------------
// tf32 helpers
// ---------------------------------------------------------------------------
__device__ __forceinline__ unsigned tf32_rna(float x) {
    unsigned r; asm("cvt.rna.tf32.f32 %0, %1;" : "=r"(r) : "f"(x)); return r;
}
__device__ __forceinline__ void tf32_split(float x, float& hi, float& lo) {
    unsigned h = tf32_rna(x);
    hi = __uint_as_float(h);
    lo = __uint_as_float(tf32_rna(x - hi));
}
__device__ __forceinline__ void mma_tf32(float c[4],
                                         const unsigned a[4],
                                         unsigned b0, unsigned b1) {
    asm volatile(
        "mma.sync.aligned.m16n8k8.row.col.f32.tf32.tf32.f32 "
        "{%0,%1,%2,%3}, {%4,%5,%6,%7}, {%8,%9}, {%0,%1,%2,%3};"
        : "+f"(c[0]), "+f"(c[1]), "+f"(c[2]), "+f"(c[3])
        : "r"(a[0]), "r"(a[1]), "r"(a[2]), "r"(a[3]), "r"(b0), "r"(b1));
}
__device__ __forceinline__ unsigned fu(float x) { return __float_as_uint(x); }

// Write one split value into the Xf fragment layout.
__device__ __forceinline__ void xf_write(float* xf, int k, int n, float v) {
    const int ksg = k >> 3;
    const int r7  = k & 7;
    const int tig = r7 & 3;
    const int off = (r7 < 4) ? 0 : 2;
    float h, l; tf32_split(v, h, l);
    *(float2*)&xf[(((ksg * 128 + n) * 4 + tig) << 2) + off] = make_float2(h, l);
}

// ---------------------------------------------------------------------------
// Kernel 1: g[b] = sum_l item_embedding[items[b,l]]; writes Xf frag layout.
// (DRAM-saturated random gather: ~86 MB compulsory @ ~3.9-4 TB/s.)
// ---------------------------------------------------------------------------
__global__ void __launch_bounds__(256) gather_sum_kernel(
    const float* __restrict__ emb,
    const void* __restrict__ items_raw,
    float* __restrict__ xf)
{
    const int b    = blockIdx.x;
    const int t    = threadIdx.x;
    const int w    = t >> 5;
    const int lane = t & 31;

    __shared__ int sidx[SEQL];
    __shared__ int mode64;
    __shared__ float4 spart[8][32];

    if (t == 0) {
        // int64 storage => odd int32 words of first 16 elements are all zero
        const int* p = (const int*)items_raw;
        int ok = 1;
        #pragma unroll
        for (int i = 0; i < 16; i++) ok &= (p[2 * i + 1] == 0);
        mode64 = ok;
    }
    __syncthreads();

    if (t < SEQL) {
        if (mode64) sidx[t] = (int)((const long long*)items_raw)[(long long)b * SEQL + t];
        else        sidx[t] = ((const int*)items_raw)[b * SEQL + t];
    }
    __syncthreads();

    float4 acc[5], v[5];
    #pragma unroll
    for (int j = 0; j < 5; j++) acc[j] = make_float4(0.f, 0.f, 0.f, 0.f);

    #pragma unroll
    for (int j = 0; j < 5; j++)
        v[j] = *(const float4*)&emb[(size_t)sidx[w + 8 * j] * DIM + lane * 4];

    #pragma unroll
    for (int s = 0; s < 5; s++) {
        float4 nv[5];
        if (s < 4) {
            #pragma unroll
            for (int j = 0; j < 5; j++)
                nv[j] = *(const float4*)&emb[(size_t)sidx[w + 8 * (5 * (s + 1) + j)] * DIM + lane * 4];
        }
        #pragma unroll
        for (int j = 0; j < 5; j++) {
            acc[j].x += v[j].x; acc[j].y += v[j].y;
            acc[j].z += v[j].z; acc[j].w += v[j].w;
        }
        if (s < 4) {
            #pragma unroll
            for (int j = 0; j < 5; j++) v[j] = nv[j];
        }
    }

    float4 s4;
    s4.x = ((acc[0].x + acc[1].x) + (acc[2].x + acc[3].x)) + acc[4].x;
    s4.y = ((acc[0].y + acc[1].y) + (acc[2].y + acc[3].y)) + acc[4].y;
    s4.z = ((acc[0].z + acc[1].z) + (acc[2].z + acc[3].z)) + acc[4].z;
    s4.w = ((acc[0].w + acc[1].w) + (acc[2].w + acc[3].w)) + acc[4].w;

    spart[w][lane] = s4;
    __syncthreads();
    if (w < 4) {
        float4 a = spart[w][lane], c = spart[w + 4][lane];
        a.x += c.x; a.y += c.y; a.z += c.z; a.w += c.w;
        spart[w][lane] = a;
    }
    __syncthreads();
    if (w < 2) {
        float4 a = spart[w][lane], c = spart[w + 2][lane];
        a.x += c.x; a.y += c.y; a.z += c.z; a.w += c.w;
        spart[w][lane] = a;
    }
    __syncthreads();
    if (w == 0) {
        float4 a = spart[0][lane], c = spart[1][lane];
        a.x += c.x; a.y += c.y; a.z += c.z; a.w += c.w;
        float av[4] = {a.x, a.y, a.z, a.w};
        #pragma unroll
        for (int j = 0; j < 4; j++)
            xf_write(xf, b, lane * 4 + j, av[j]);
    }
}

// ---------------------------------------------------------------------------
// Kernel 2: tensor-core 3xTF32 GEMM partial (BM=32, K-split=8):
//   part[split][m0:m0+32][:] (+)= A[m0:m0+32, k0:k0+128] @ X[k0:k0+128, :]
// grid = 256 blocks (32 m-groups x 8 K-splits), 256 threads (8 warps).
//  - BM=32 halves per-GEMM L2 B-traffic vs BM=16 (64MB -> 32MB).
//  - Per warp per kstep: 4 LDS.128 (A frags, 2 m-tiles) + 12 MMA + 2 LDG.128
//    -> issue time per kstep ~2x R11, so the 4-deep B ring now covers L2 lat.
//  - 12 independent accumulator chains/warp (hh/hl/lh x mt x nt).
//  Fragment<->matrix mappings identical to the R10/R11-verified kernels.
// ---------------------------------------------------------------------------
__global__ void __launch_bounds__(256) gemm_tc_kernel(
    const float* __restrict__ A,
    const float4* __restrict__ Xf,   // [128 ksteps][128 n][4 tig]
    float* __restrict__ part)
{
    const int mg    = blockIdx.x >> 3;   // 0..31
    const int split = blockIdx.x & 7;    // 0..7
    const int m0 = mg * 32;
    const int k0 = split * 128;

    __shared__ __align__(16) float sAfh[16][2][32][4];   // 16 KB
    __shared__ __align__(16) float sAfl[16][2][32][4];   // 16 KB

    // ---- prologue: load + split + fragment-arrange A[32][128] ----
    {
        const int r  = threadIdx.x >> 3;     // 0..31 row
        const int kb = threadIdx.x & 7;      // 16 k each
        const float* ar = A + (size_t)(m0 + r) * 1024 + k0 + kb * 16;
        const int mt   = r >> 4;
        const int ri   = r & 15;
        const int ehi  = (ri >= 8) ? 1 : 0;
        const int gid8 = ri & 7;
        #pragma unroll
        for (int j4 = 0; j4 < 4; j4++) {
            const float4 vv = *(const float4*)&ar[j4 * 4];
            const float va[4] = {vv.x, vv.y, vv.z, vv.w};
            #pragma unroll
            for (int e = 0; e < 4; e++) {
                const int kq   = kb * 16 + j4 * 4 + e;   // 0..127
                const int ks   = kq >> 3;
                const int kt   = kq & 7;
                const int lane = gid8 * 4 + (kt & 3);
                const int elem = ehi + ((kt >= 4) ? 2 : 0);
                float h, l; tf32_split(va[e], h, l);
                sAfh[ks][mt][lane][elem] = h;
                sAfl[ks][mt][lane][elem] = l;
            }
        }
    }
    __syncthreads();

    const int lane = threadIdx.x & 31;
    const int warp = threadIdx.x >> 5;   // 0..7
    const int gid  = lane >> 2;
    const int tig  = lane & 3;
    const int nb   = warp * 16;

    float ahh[2][2][4], ahl[2][2][4], alh[2][2][4];
    #pragma unroll
    for (int mt = 0; mt < 2; mt++)
        #pragma unroll
        for (int nt = 0; nt < 2; nt++)
            #pragma unroll
            for (int i = 0; i < 4; i++) {
                ahh[mt][nt][i] = 0.f; ahl[mt][nt][i] = 0.f; alh[mt][nt][i] = 0.f;
            }

    const float4* Xq = Xf + (size_t)(split * 16) * 128 * 4;
    const int n0 = nb + gid;
    const int n1 = nb + 8 + gid;

    // ring prefetch: 4 ksteps deep
    float4 br[4][2];
    #pragma unroll
    for (int q = 0; q < 4; q++) {
        br[q][0] = Xq[(q * 128 + n0) * 4 + tig];
        br[q][1] = Xq[(q * 128 + n1) * 4 + tig];
    }

    #pragma unroll 1
    for (int ksb = 0; ksb < 16; ksb += 4) {
        #pragma unroll
        for (int q = 0; q < 4; q++) {
            const int ks = ksb + q;
            unsigned ah[2][4], al[2][4];
            #pragma unroll
            for (int mt = 0; mt < 2; mt++) {
                const float4 h4 = *(const float4*)&sAfh[ks][mt][lane][0];
                const float4 l4 = *(const float4*)&sAfl[ks][mt][lane][0];
                ah[mt][0] = fu(h4.x); ah[mt][1] = fu(h4.y); ah[mt][2] = fu(h4.z); ah[mt][3] = fu(h4.w);
                al[mt][0] = fu(l4.x); al[mt][1] = fu(l4.y); al[mt][2] = fu(l4.z); al[mt][3] = fu(l4.w);
            }
            #pragma unroll
            for (int nt = 0; nt < 2; nt++) {
                const float4 b = br[q][nt];
                #pragma unroll
                for (int mt = 0; mt < 2; mt++) {
                    mma_tf32(ahh[mt][nt], ah[mt], fu(b.x), fu(b.z));   // hi*hi
                    mma_tf32(ahl[mt][nt], ah[mt], fu(b.y), fu(b.w));   // hi*lo
                    mma_tf32(alh[mt][nt], al[mt], fu(b.x), fu(b.z));   // lo*hi
                }
            }
            if (ks + 4 < 16) {
                br[q][0] = Xq[((ks + 4) * 128 + n0) * 4 + tig];
                br[q][1] = Xq[((ks + 4) * 128 + n1) * 4 + tig];
            }
        }
    }

    // ---- epilogue: write partials (R10-verified C mapping) ----
    float* pb = part + (size_t)split * BATCH * DIM;
    #pragma unroll
    for (int mt = 0; mt < 2; mt++) {
        const int r = m0 + mt * 16 + gid;
        #pragma unroll
        for (int nt = 0; nt < 2; nt++) {
            const int n = nb + nt * 8 + 2 * tig;
            const float c0 = ahh[mt][nt][0] + ahl[mt][nt][0] + alh[mt][nt][0];
            const float c1 = ahh[mt][nt][1] + ahl[mt][nt][1] + alh[mt][nt][1];
            const float c2 = ahh[mt][nt][2] + ahl[mt][nt][2] + alh[mt][nt][2];
            const float c3 = ahh[mt][nt][3] + ahl[mt][nt][3] + alh[mt][nt][3];
            pb[r * DIM + n]           = c0;
            pb[r * DIM + n + 1]       = c1;
            pb[(r + 8) * DIM + n]     = c2;
            pb[(r + 8) * DIM + n + 1] = c3;
        }
    }
}

// ---------------------------------------------------------------------------
// Kernel 3: reduce 8 K-split partials.
//  MODE 0: re-split to Xf fragment layout (feeds next GEMM).
//  MODE 1: fused selu + row L2-normalize -> final output.
// ---------------------------------------------------------------------------
template <int MODE>
__global__ void __launch_bounds__(128) reduce_kernel(
    const float* __restrict__ part,
    float* __restrict__ outv)
{
    const int m = blockIdx.x;
    const int n = threadIdx.x;

    float s = 0.f;
    #pragma unroll
    for (int sp = 0; sp < 8; sp++)
        s += part[((size_t)sp * BATCH + m) * DIM + n];

    if (MODE == 0) {
        xf_write(outv, m, n, s);
    } else {
        const float SELU_SCALE = 1.0507009873554804934f;
        const float SELU_ALPHA = 1.6732632423543772848f;
        const float sv = (s > 0.f) ? SELU_SCALE * s
                                   : SELU_SCALE * SELU_ALPHA * (expf(s) - 1.f);
        float sq = sv * sv;
        #pragma unroll
        for (int o = 16; o; o >>= 1) sq += __shfl_xor_sync(0xFFFFFFFFu, sq, o);
        __shared__ float ws[4];
        if ((n & 31) == 0) ws[n >> 5] = sq;
        __syncthreads();
        const float tot = ws[0] + ws[1] + ws[2] + ws[3];
        outv[m * DIM + n] = sv * rsqrtf(tot);
    }
}

// ---------------------------------------------------------------------------
// Launch: gather(->Xf) -> TC-GEMM(A) -> reduce(->Xf) -> TC-GEMM(D)
//         -> reduce+selu+norm
// (attention/entmax path is analytically identity on g: scores constant
//  along L, entmax of a constant is uniform, sum(p)*g = g)
// ---------------------------------------------------------------------------
extern "C" void kernel_launch(void* const* d_in, const int* in_sizes, int n_in,
                              void* d_out, int out_size)
{
    const float* emb   = (const float*)d_in[0];  // [500000, 128]
    const void*  items = d_in[1];                // [1024, 200] int64/int32
    const float* Amat  = (const float*)d_in[2];  // [1024, 1024]
    const float* Dmat  = (const float*)d_in[3];  // [1024, 1024]
    float* out = (float*)d_out;                  // [1024, 128]

    float *xf0, *xf1, *part;
    cudaGetSymbolAddress((void**)&xf0, xf0_buf);
    cudaGetSymbolAddress((void**)&xf1, xf1_buf);
    cudaGetSymbolAddress((void**)&part, part_buf);

    gather_sum_kernel<<<BATCH, 256>>>(emb, items, xf0);

    gemm_tc_kernel<<<256, 256>>>(Amat, (const float4*)xf0, part);  // A@g
    reduce_kernel<0><<<BATCH, DIM>>>(part, xf1);                   // -> Xf(ag)

    gemm_tc_kernel<<<256, 256>>>(Dmat, (const float4*)xf1, part);  // D@ag
    reduce_kernel<1><<<BATCH, DIM>>>(part, out);                   // selu+norm
}

// round 13
// speedup vs baseline: 1.0948x; 1.0948x over previous
#include <cuda_runtime.h>
#include <cuda_bf16.h>
#include <cstdint>

#define BATCH 1024
#define SEQL  200
#define DIM   128

// Scratch (allocation-free rule: __device__ globals)
// Xb layout: [64 ksteps][128 n][4 tig] uint4 = {b0hi, b1hi, b0lo, b1lo}
// (bf16x2 each). kstep covers k = ks*16 .. ks*16+15; within a fragment:
//   b0 = rows 2*tig,2*tig+1; b1 = rows 2*tig+8,2*tig+9; col = gid.
__device__ unsigned xb0_buf[64 * 128 * 16];        // g   (512 KB)
__device__ unsigned xb1_buf[64 * 128 * 16];        // ag  (512 KB)
__device__ float    part_buf[8 * BATCH * DIM];     // 8 K-split partials (4 MB)

// ---------------------------------------------------------------------------
// bf16 split helpers (Ootomo 3-product scheme: hh + hl + lh)
// ---------------------------------------------------------------------------
__device__ __forceinline__ void bf16_split(float v, unsigned short& h, unsigned short& l) {
    __nv_bfloat16 hb = __float2bfloat16(v);
    __nv_bfloat16 lb = __float2bfloat16(v - __bfloat162float(hb));
    h = *(unsigned short*)&hb;
    l = *(unsigned short*)&lb;
}
__device__ __forceinline__ void mma_bf16(float c[4],
                                         const unsigned a[4],
                                         unsigned b0, unsigned b1) {
    asm volatile(
        "mma.sync.aligned.m16n8k16.row.col.f32.bf16.bf16.f32 "
        "{%0,%1,%2,%3}, {%4,%5,%6,%7}, {%8,%9}, {%0,%1,%2,%3};"
        : "+f"(c[0]), "+f"(c[1]), "+f"(c[2]), "+f"(c[3])
        : "r"(a[0]), "r"(a[1]), "r"(a[2]), "r"(a[3]), "r"(b0), "r"(b1));
}

// Write one value of X[k][n] into the Xb fragment layout (hi/lo bf16).
__device__ __forceinline__ void xb_write(unsigned* xb, int k, int n, float v) {
    const int ks  = k >> 4;
    const int r   = k & 15;
    const int reg = (r >= 8) ? 1 : 0;
    const int rr  = r & 7;
    const int tig = rr >> 1;
    const int e   = rr & 1;
    unsigned short h, l; bf16_split(v, h, l);
    unsigned short* s = (unsigned short*)(xb + (((ks * 128 + n) * 4 + tig) << 2));
    s[reg * 2 + e]     = h;   // uint4.x/.y
    s[4 + reg * 2 + e] = l;   // uint4.z/.w
}

// ---------------------------------------------------------------------------
// Kernel 1: g[b] = sum_l item_embedding[items[b,l]]; writes Xb frag layout.
// (DRAM-saturated random gather: ~86 MB compulsory @ ~3.9-4 TB/s.)
// ---------------------------------------------------------------------------
__global__ void __launch_bounds__(256) gather_sum_kernel(
    const float* __restrict__ emb,
    const void* __restrict__ items_raw,
    unsigned* __restrict__ xb)
{
    const int b    = blockIdx.x;
    const int t    = threadIdx.x;
    const int w    = t >> 5;
    const int lane = t & 31;

    __shared__ int sidx[SEQL];
    __shared__ int mode64;
    __shared__ float4 spart[8][32];

    if (t == 0) {
        // int64 storage => odd int32 words of first 16 elements are all zero
        const int* p = (const int*)items_raw;
        int ok = 1;
        #pragma unroll
        for (int i = 0; i < 16; i++) ok &= (p[2 * i + 1] == 0);
        mode64 = ok;
    }
    __syncthreads();

    if (t < SEQL) {
        if (mode64) sidx[t] = (int)((const long long*)items_raw)[(long long)b * SEQL + t];
        else        sidx[t] = ((const int*)items_raw)[b * SEQL + t];
    }
    __syncthreads();

    float4 acc[5], v[5];
    #pragma unroll
    for (int j = 0; j < 5; j++) acc[j] = make_float4(0.f, 0.f, 0.f, 0.f);

    #pragma unroll
    for (int j = 0; j < 5; j++)
        v[j] = *(const float4*)&emb[(size_t)sidx[w + 8 * j] * DIM + lane * 4];

    #pragma unroll
    for (int s = 0; s < 5; s++) {
        float4 nv[5];
        if (s < 4) {
            #pragma unroll
            for (int j = 0; j < 5; j++)
                nv[j] = *(const float4*)&emb[(size_t)sidx[w + 8 * (5 * (s + 1) + j)] * DIM + lane * 4];
        }
        #pragma unroll
        for (int j = 0; j < 5; j++) {
            acc[j].x += v[j].x; acc[j].y += v[j].y;
            acc[j].z += v[j].z; acc[j].w += v[j].w;
        }
        if (s < 4) {
            #pragma unroll
            for (int j = 0; j < 5; j++) v[j] = nv[j];
        }
    }

    float4 s4;
    s4.x = ((acc[0].x + acc[1].x) + (acc[2].x + acc[3].x)) + acc[4].x;
    s4.y = ((acc[0].y + acc[1].y) + (acc[2].y + acc[3].y)) + acc[4].y;
    s4.z = ((acc[0].z + acc[1].z) + (acc[2].z + acc[3].z)) + acc[4].z;
    s4.w = ((acc[0].w + acc[1].w) + (acc[2].w + acc[3].w)) + acc[4].w;

    spart[w][lane] = s4;
    __syncthreads();
    if (w < 4) {
        float4 a = spart[w][lane], c = spart[w + 4][lane];
        a.x += c.x; a.y += c.y; a.z += c.z; a.w += c.w;
        spart[w][lane] = a;
    }
    __syncthreads();
    if (w < 2) {
        float4 a = spart[w][lane], c = spart[w + 2][lane];
        a.x += c.x; a.y += c.y; a.z += c.z; a.w += c.w;
        spart[w][lane] = a;
    }
    __syncthreads();
    if (w == 0) {
        float4 a = spart[0][lane], c = spart[1][lane];
        a.x += c.x; a.y += c.y; a.z += c.z; a.w += c.w;
        const float av[4] = {a.x, a.y, a.z, a.w};
        #pragma unroll
        for (int j = 0; j < 4; j++)
            xb_write(xb, b, lane * 4 + j, av[j]);
    }
}

// ---------------------------------------------------------------------------
// Kernel 2: tensor-core 3xBF16 (Ootomo) GEMM partial (BM=32, K-split=8):
//   part[split][m0:m0+32][:] (+)= A[m0:m0+32, k0:k0+128] @ X[k0:k0+128, :]
// grid = 256 blocks (32 m-groups x 8 K-splits), 256 threads (8 warps).
// m16n8k16 bf16 MMA: K=16 per instruction -> half the MMA count of tf32 k8.
// Products: hh into chh, hl+lh into ccor (merged accumulator).
// A split once in prologue into fragment-ordered smem (2 LDS.128/mt/kstep).
// B pre-arranged in gmem: 1 LDG.128 per nt per kstep, 4-deep ring prefetch.
// ---------------------------------------------------------------------------
__global__ void __launch_bounds__(256) gemm_tc_kernel(
    const float* __restrict__ A,
    const uint4* __restrict__ Xb,    // [64 ksteps][128 n][4 tig]
    float* __restrict__ part)
{
    const int mg    = blockIdx.x >> 3;   // 0..31
    const int split = blockIdx.x & 7;    // 0..7
    const int m0 = mg * 32;
    const int k0 = split * 128;

    __shared__ __align__(16) unsigned sAfh[8][2][32][4];   // 8 KB
    __shared__ __align__(16) unsigned sAfl[8][2][32][4];   // 8 KB

    // ---- prologue: load + bf16-split + fragment-arrange A[32][128] ----
    {
        const int r  = threadIdx.x >> 3;     // 0..31 row
        const int kb = threadIdx.x & 7;      // 16 k each
        const float* ar = A + (size_t)(m0 + r) * 1024 + k0 + kb * 16;
        const int mt   = r >> 4;
        const int ri   = r & 15;
        const int ehi  = (ri >= 8) ? 1 : 0;
        const int gid8 = ri & 7;
        #pragma unroll
        for (int j4 = 0; j4 < 4; j4++) {
            const float4 vv = *(const float4*)&ar[j4 * 4];
            const float va[4] = {vv.x, vv.y, vv.z, vv.w};
            #pragma unroll
            for (int e4 = 0; e4 < 4; e4++) {
                const int kq  = kb * 16 + j4 * 4 + e4;   // 0..127
                const int ks  = kq >> 4;
                const int kt  = kq & 15;
                const int khi = (kt >= 8) ? 1 : 0;
                const int rr  = kt & 7;
                const int tig = rr >> 1;
                const int ke  = rr & 1;
                const int reg = ehi + 2 * khi;           // a0..a3
                const int lane = gid8 * 4 + tig;
                unsigned short h, l; bf16_split(va[e4], h, l);
                ((unsigned short*)&sAfh[ks][mt][lane][reg])[ke] = h;
                ((unsigned short*)&sAfl[ks][mt][lane][reg])[ke] = l;
            }
        }
    }
    __syncthreads();

    const int lane = threadIdx.x & 31;
    const int warp = threadIdx.x >> 5;   // 0..7
    const int gid  = lane >> 2;
    const int tig  = lane & 3;
    const int nb   = warp * 16;

    float chh[2][2][4], cor[2][2][4];
    #pragma unroll
    for (int mt = 0; mt < 2; mt++)
        #pragma unroll
        for (int nt = 0; nt < 2; nt++)
            #pragma unroll
            for (int i = 0; i < 4; i++) { chh[mt][nt][i] = 0.f; cor[mt][nt][i] = 0.f; }

    const uint4* Xq = Xb + (size_t)(split * 8) * 128 * 4;
    const int n0 = nb + gid;
    const int n1 = nb + 8 + gid;

    // ring prefetch: 4 ksteps deep (of 8)
    uint4 br[4][2];
    #pragma unroll
    for (int q = 0; q < 4; q++) {
        br[q][0] = Xq[(q * 128 + n0) * 4 + tig];
        br[q][1] = Xq[(q * 128 + n1) * 4 + tig];
    }

    #pragma unroll 1
    for (int ksb = 0; ksb < 8; ksb += 4) {
        #pragma unroll
        for (int q = 0; q < 4; q++) {
            const int ks = ksb + q;
            uint4 ah4[2], al4[2];
            #pragma unroll
            for (int mt = 0; mt < 2; mt++) {
                ah4[mt] = *(const uint4*)&sAfh[ks][mt][lane][0];
                al4[mt] = *(const uint4*)&sAfl[ks][mt][lane][0];
            }
            #pragma unroll
            for (int nt = 0; nt < 2; nt++) {
                const uint4 b = br[q][nt];
                #pragma unroll
                for (int mt = 0; mt < 2; mt++) {
                    const unsigned ah[4] = {ah4[mt].x, ah4[mt].y, ah4[mt].z, ah4[mt].w};
                    const unsigned al[4] = {al4[mt].x, al4[mt].y, al4[mt].z, al4[mt].w};
                    mma_bf16(chh[mt][nt], ah, b.x, b.y);   // hi*hi
                    mma_bf16(cor[mt][nt], ah, b.z, b.w);   // hi*lo
                    mma_bf16(cor[mt][nt], al, b.x, b.y);   // lo*hi
                }
            }
            if (ks + 4 < 8) {
                br[q][0] = Xq[((ks + 4) * 128 + n0) * 4 + tig];
                br[q][1] = Xq[((ks + 4) * 128 + n1) * 4 + tig];
            }
        }
    }

    // ---- epilogue: write partials (standard m16n8 C mapping) ----
    float* pb = part + (size_t)split * BATCH * DIM;
    #pragma unroll
    for (int mt = 0; mt < 2; mt++) {
        const int r = m0 + mt * 16 + gid;
        #pragma unroll
        for (int nt = 0; nt < 2; nt++) {
            const int n = nb + nt * 8 + 2 * tig;
            pb[r * DIM + n]           = chh[mt][nt][0] + cor[mt][nt][0];
            pb[r * DIM + n + 1]       = chh[mt][nt][1] + cor[mt][nt][1];
            pb[(r + 8) * DIM + n]     = chh[mt][nt][2] + cor[mt][nt][2];
            pb[(r + 8) * DIM + n + 1] = chh[mt][nt][3] + cor[mt][nt][3];
        }
    }
}

// ---------------------------------------------------------------------------
// Kernel 3: reduce 8 K-split partials.
//  MODE 0: re-split to Xb fragment layout (feeds next GEMM).
//  MODE 1: fused selu + row L2-normalize -> final output.
// ---------------------------------------------------------------------------
template <int MODE>
__global__ void __launch_bounds__(128) reduce_kernel(
    const float* __restrict__ part,
    void* __restrict__ outv)
{
    const int m = blockIdx.x;
    const int n = threadIdx.x;

    float s = 0.f;
    #pragma unroll
    for (int sp = 0; sp < 8; sp++)
        s += part[((size_t)sp * BATCH + m) * DIM + n];

    if (MODE == 0) {
        xb_write((unsigned*)outv, m, n, s);
    } else {
        const float SELU_SCALE = 1.0507009873554804934f;
        const float SELU_ALPHA = 1.6732632423543772848f;
        const float sv = (s > 0.f) ? SELU_SCALE * s
                                   : SELU_SCALE * SELU_ALPHA * (expf(s) - 1.f);
        float sq = sv * sv;
        #pragma unroll
        for (int o = 16; o; o >>= 1) sq += __shfl_xor_sync(0xFFFFFFFFu, sq, o);
        __shared__ float ws[4];
        if ((n & 31) == 0) ws[n >> 5] = sq;
        __syncthreads();
        const float tot = ws[0] + ws[1] + ws[2] + ws[3];
        ((float*)outv)[m * DIM + n] = sv * rsqrtf(tot);
    }
}

// ---------------------------------------------------------------------------
// Launch: gather(->Xb) -> TC-GEMM(A) -> reduce(->Xb) -> TC-GEMM(D)
//         -> reduce+selu+norm
// (attention/entmax path is analytically identity on g: scores constant
//  along L, entmax of a constant is uniform, sum(p)*g = g)
// ---------------------------------------------------------------------------
extern "C" void kernel_launch(void* const* d_in, const int* in_sizes, int n_in,
                              void* d_out, int out_size)
{
    const float* emb   = (const float*)d_in[0];  // [500000, 128]
    const void*  items = d_in[1];                // [1024, 200] int64/int32
    const float* Amat  = (const float*)d_in[2];  // [1024, 1024]
    const float* Dmat  = (const float*)d_in[3];  // [1024, 1024]
    float* out = (float*)d_out;                  // [1024, 128]

    unsigned *xb0, *xb1;
    float *part;
    cudaGetSymbolAddress((void**)&xb0, xb0_buf);
    cudaGetSymbolAddress((void**)&xb1, xb1_buf);
    cudaGetSymbolAddress((void**)&part, part_buf);

    gather_sum_kernel<<<BATCH, 256>>>(emb, items, xb0);

    gemm_tc_kernel<<<256, 256>>>(Amat, (const uint4*)xb0, part);   // A@g
    reduce_kernel<0><<<BATCH, DIM>>>(part, xb1);                   // -> Xb(ag)

    gemm_tc_kernel<<<256, 256>>>(Dmat, (const uint4*)xb1, part);   // D@ag
    reduce_kernel<1><<<BATCH, DIM>>>(part, out);                   // selu+norm
}

// round 15
// speedup vs baseline: 1.2583x; 1.1493x over previous
#include <cuda_runtime.h>
#include <cuda_bf16.h>
#include <cstdint>

#define BATCH 1024
#define SEQL  200
#define DIM   128

// Scratch (allocation-free rule: __device__ globals)
// Xb layout: [64 ksteps][128 n][4 tig] uint4 = {b0hi, b1hi, b0lo, b1lo}
// (bf16x2 each). kstep covers k = ks*16 .. ks*16+15; within a fragment:
//   b0 = rows 2*tig,2*tig+1; b1 = rows 2*tig+8,2*tig+9; col = gid.
__device__ unsigned xb0_buf[64 * 128 * 16];        // g   (512 KB)
__device__ unsigned xb1_buf[64 * 128 * 16];        // ag  (512 KB)
__device__ float    part_buf[4 * BATCH * DIM];     // 4 K-split partials (2 MB)

// ---------------------------------------------------------------------------
// bf16 split helpers (Ootomo 3-product scheme: hh + hl + lh)
// ---------------------------------------------------------------------------
__device__ __forceinline__ void bf16_split(float v, unsigned short& h, unsigned short& l) {
    __nv_bfloat16 hb = __float2bfloat16(v);
    __nv_bfloat16 lb = __float2bfloat16(v - __bfloat162float(hb));
    h = *(unsigned short*)&hb;
    l = *(unsigned short*)&lb;
}
// split a float2 (k-even, k-odd) into packed hi-uint and lo-uint
__device__ __forceinline__ void split2(float2 f, unsigned& h, unsigned& l) {
    unsigned short h0, l0, h1, l1;
    bf16_split(f.x, h0, l0);
    bf16_split(f.y, h1, l1);
    h = (unsigned)h0 | ((unsigned)h1 << 16);
    l = (unsigned)l0 | ((unsigned)l1 << 16);
}
__device__ __forceinline__ void mma_bf16(float c[4],
                                         const unsigned a[4],
                                         unsigned b0, unsigned b1) {
    asm volatile(
        "mma.sync.aligned.m16n8k16.row.col.f32.bf16.bf16.f32 "
        "{%0,%1,%2,%3}, {%4,%5,%6,%7}, {%8,%9}, {%0,%1,%2,%3};"
        : "+f"(c[0]), "+f"(c[1]), "+f"(c[2]), "+f"(c[3])
        : "r"(a[0]), "r"(a[1]), "r"(a[2]), "r"(a[3]), "r"(b0), "r"(b1));
}

// Write one value of X[k][n] into the Xb fragment layout (hi/lo bf16).
__device__ __forceinline__ void xb_write(unsigned* xb, int k, int n, float v) {
    const int ks  = k >> 4;
    const int r   = k & 15;
    const int reg = (r >= 8) ? 1 : 0;
    const int rr  = r & 7;
    const int tig = rr >> 1;
    const int e   = rr & 1;
    unsigned short h, l; bf16_split(v, h, l);
    unsigned short* s = (unsigned short*)(xb + (((ks * 128 + n) * 4 + tig) << 2));
    s[reg * 2 + e]     = h;   // uint4.x/.y
    s[4 + reg * 2 + e] = l;   // uint4.z/.w
}

// ---------------------------------------------------------------------------
// Kernel 1: g[b] = sum_l item_embedding[items[b,l]]; writes Xb frag layout.
// (DRAM-saturated random gather: ~86 MB compulsory @ ~3.9-4 TB/s.)
// ---------------------------------------------------------------------------
__global__ void __launch_bounds__(256) gather_sum_kernel(
    const float* __restrict__ emb,
    const void* __restrict__ items_raw,
    unsigned* __restrict__ xb)
{
    const int b    = blockIdx.x;
    const int t    = threadIdx.x;
    const int w    = t >> 5;
    const int lane = t & 31;

    __shared__ int sidx[SEQL];
    __shared__ int mode64;
    __shared__ float4 spart[8][32];

    if (t == 0) {
        // int64 storage => odd int32 words of first 16 elements are all zero
        const int* p = (const int*)items_raw;
        int ok = 1;
        #pragma unroll
        for (int i = 0; i < 16; i++) ok &= (p[2 * i + 1] == 0);
        mode64 = ok;
    }
    __syncthreads();

    if (t < SEQL) {
        if (mode64) sidx[t] = (int)((const long long*)items_raw)[(long long)b * SEQL + t];
        else        sidx[t] = ((const int*)items_raw)[b * SEQL + t];
    }
    __syncthreads();

    float4 acc[5], v[5];
    #pragma unroll
    for (int j = 0; j < 5; j++) acc[j] = make_float4(0.f, 0.f, 0.f, 0.f);

    #pragma unroll
    for (int j = 0; j < 5; j++)
        v[j] = *(const float4*)&emb[(size_t)sidx[w + 8 * j] * DIM + lane * 4];

    #pragma unroll
    for (int s = 0; s < 5; s++) {
        float4 nv[5];
        if (s < 4) {
            #pragma unroll
            for (int j = 0; j < 5; j++)
                nv[j] = *(const float4*)&emb[(size_t)sidx[w + 8 * (5 * (s + 1) + j)] * DIM + lane * 4];
        }
        #pragma unroll
        for (int j = 0; j < 5; j++) {
            acc[j].x += v[j].x; acc[j].y += v[j].y;
            acc[j].z += v[j].z; acc[j].w += v[j].w;
        }
        if (s < 4) {
            #pragma unroll
            for (int j = 0; j < 5; j++) v[j] = nv[j];
        }
    }

    float4 s4;
    s4.x = ((acc[0].x + acc[1].x) + (acc[2].x + acc[3].x)) + acc[4].x;
    s4.y = ((acc[0].y + acc[1].y) + (acc[2].y + acc[3].y)) + acc[4].y;
    s4.z = ((acc[0].z + acc[1].z) + (acc[2].z + acc[3].z)) + acc[4].z;
    s4.w = ((acc[0].w + acc[1].w) + (acc[2].w + acc[3].w)) + acc[4].w;

    spart[w][lane] = s4;
    __syncthreads();
    if (w < 4) {
        float4 a = spart[w][lane], c = spart[w + 4][lane];
        a.x += c.x; a.y += c.y; a.z += c.z; a.w += c.w;
        spart[w][lane] = a;
    }
    __syncthreads();
    if (w < 2) {
        float4 a = spart[w][lane], c = spart[w + 2][lane];
        a.x += c.x; a.y += c.y; a.z += c.z; a.w += c.w;
        spart[w][lane] = a;
    }
    __syncthreads();
    if (w == 0) {
        float4 a = spart[0][lane], c = spart[1][lane];
        a.x += c.x; a.y += c.y; a.z += c.z; a.w += c.w;
        const float av[4] = {a.x, a.y, a.z, a.w};
        #pragma unroll
        for (int j = 0; j < 4; j++)
            xb_write(xb, b, lane * 4 + j, av[j]);
    }
}

// ---------------------------------------------------------------------------
// Kernel 2: tensor-core 3xBF16 (Ootomo) GEMM partial (BM=32, K-split=4):
//   part[split][m0:m0+32][:] (+)= A[m0:m0+32, k0:k0+256] @ X[k0:k0+256, :]
// grid = 128 blocks (32 m-groups x 4 K-splits) = ONE wave, 256 threads.
//
// Prologue processes the 32x256 A slice in TWO 128-col halves through a
// 16 KB fp32 staging buffer (smem budget: 16+16+16 = 48 KB static):
//   LDG h0 -> STS -> sync -> [LDG h1 into regs | convert ks 0-7] -> sync
//   -> STS h1 -> sync -> convert ks 8-15 -> sync
// Conversion: per (ks,mt,lane) tuple, 4 LDS.64 -> register split/pack ->
// 2 STS.128 (full uint4 fragments). Fragment semantics identical to the
// R13-verified layout (reg = rowhi + 2*khi, ushort0 = k even).
// Mainloop: 16 ksteps; per warp/kstep 4 LDS.128 + 12 MMA + 2 LDG.128,
// B ring-prefetched 4 deep from gmem fragment layout.
// ---------------------------------------------------------------------------
__global__ void __launch_bounds__(256) gemm_tc_kernel(
    const float* __restrict__ A,
    const uint4* __restrict__ Xb,    // [64 ksteps][128 n][4 tig]
    float* __restrict__ part)
{
    const int mg    = blockIdx.x >> 2;   // 0..31
    const int split = blockIdx.x & 3;    // 0..3
    const int m0 = mg * 32;
    const int k0 = split * 256;

    __shared__ __align__(16) float    sAraw[32][128];       // 16 KB (one half)
    __shared__ __align__(16) unsigned sAfh[16][2][32][4];   // 16 KB
    __shared__ __align__(16) unsigned sAfl[16][2][32][4];   // 16 KB

    const int tid = threadIdx.x;

    // per-thread load coords (one half = 1024 float4 = 4 per thread)
    // u = tid + 256*j : row = u>>5 (0..31), c4 = u&31 (float4 col in half)
    float4 ld[4];

    // ---- half 0: LDG + STS ----
    #pragma unroll
    for (int j = 0; j < 4; j++) {
        const int u = tid + 256 * j;
        ld[j] = *(const float4*)&A[(size_t)(m0 + (u >> 5)) * 1024 + k0 + (u & 31) * 4];
    }
    #pragma unroll
    for (int j = 0; j < 4; j++) {
        const int u = tid + 256 * j;
        *(float4*)&sAraw[u >> 5][(u & 31) * 4] = ld[j];
    }
    __syncthreads();

    // ---- LDG half 1 into regs (latency buried under convert of half 0) ----
    #pragma unroll
    for (int j = 0; j < 4; j++) {
        const int u = tid + 256 * j;
        ld[j] = *(const float4*)&A[(size_t)(m0 + (u >> 5)) * 1024 + k0 + 128 + (u & 31) * 4];
    }

    // ---- convert half 0: ks 0..7 (512 tuples, 2 per thread) ----
    #pragma unroll
    for (int j = 0; j < 2; j++) {
        const int idx  = tid + 256 * j;      // 0..511
        const int lane = idx & 31;
        const int mt   = (idx >> 5) & 1;
        const int ksl  = idx >> 6;           // 0..7
        const int gid8 = lane >> 2;
        const int tig  = lane & 3;
        const int r0   = mt * 16 + gid8;
        const int r1   = r0 + 8;
        const int kb2  = ksl * 16 + 2 * tig;

        const float2 f00 = *(const float2*)&sAraw[r0][kb2];
        const float2 f10 = *(const float2*)&sAraw[r1][kb2];
        const float2 f01 = *(const float2*)&sAraw[r0][kb2 + 8];
        const float2 f11 = *(const float2*)&sAraw[r1][kb2 + 8];

        uint4 hv, lv;
        split2(f00, hv.x, lv.x);   // reg0: row lo, k lo
        split2(f10, hv.y, lv.y);   // reg1: row hi, k lo
        split2(f01, hv.z, lv.z);   // reg2: row lo, k hi
        split2(f11, hv.w, lv.w);   // reg3: row hi, k hi
        *(uint4*)&sAfh[ksl][mt][lane][0] = hv;
        *(uint4*)&sAfl[ksl][mt][lane][0] = lv;
    }
    __syncthreads();

    // ---- half 1: STS ----
    #pragma unroll
    for (int j = 0; j < 4; j++) {
        const int u = tid + 256 * j;
        *(float4*)&sAraw[u >> 5][(u & 31) * 4] = ld[j];
    }
    __syncthreads();

    // ---- convert half 1: ks 8..15 ----
    #pragma unroll
    for (int j = 0; j < 2; j++) {
        const int idx  = tid + 256 * j;
        const int lane = idx & 31;
        const int mt   = (idx >> 5) & 1;
        const int ksl  = idx >> 6;           // 0..7
        const int gid8 = lane >> 2;
        const int tig  = lane & 3;
        const int r0   = mt * 16 + gid8;
        const int r1   = r0 + 8;
        const int kb2  = ksl * 16 + 2 * tig;

        const float2 f00 = *(const float2*)&sAraw[r0][kb2];
        const float2 f10 = *(const float2*)&sAraw[r1][kb2];
        const float2 f01 = *(const float2*)&sAraw[r0][kb2 + 8];
        const float2 f11 = *(const float2*)&sAraw[r1][kb2 + 8];

        uint4 hv, lv;
        split2(f00, hv.x, lv.x);
        split2(f10, hv.y, lv.y);
        split2(f01, hv.z, lv.z);
        split2(f11, hv.w, lv.w);
        *(uint4*)&sAfh[8 + ksl][mt][lane][0] = hv;
        *(uint4*)&sAfl[8 + ksl][mt][lane][0] = lv;
    }
    __syncthreads();

    const int lane = tid & 31;
    const int warp = tid >> 5;   // 0..7
    const int gid  = lane >> 2;
    const int tig  = lane & 3;
    const int nb   = warp * 16;

    float chh[2][2][4], cor[2][2][4];
    #pragma unroll
    for (int mt = 0; mt < 2; mt++)
        #pragma unroll
        for (int nt = 0; nt < 2; nt++)
            #pragma unroll
            for (int i = 0; i < 4; i++) { chh[mt][nt][i] = 0.f; cor[mt][nt][i] = 0.f; }

    const uint4* Xq = Xb + (size_t)(split * 16) * 128 * 4;
    const int n0 = nb + gid;
    const int n1 = nb + 8 + gid;

    // ring prefetch: 4 ksteps deep (of 16)
    uint4 br[4][2];
    #pragma unroll
    for (int q = 0; q < 4; q++) {
        br[q][0] = Xq[(q * 128 + n0) * 4 + tig];
        br[q][1] = Xq[(q * 128 + n1) * 4 + tig];
    }

    #pragma unroll 1
    for (int ksb = 0; ksb < 16; ksb += 4) {
        #pragma unroll
        for (int q = 0; q < 4; q++) {
            const int ks = ksb + q;
            uint4 ah4[2], al4[2];
            #pragma unroll
            for (int mt = 0; mt < 2; mt++) {
                ah4[mt] = *(const uint4*)&sAfh[ks][mt][lane][0];
                al4[mt] = *(const uint4*)&sAfl[ks][mt][lane][0];
            }
            #pragma unroll
            for (int nt = 0; nt < 2; nt++) {
                const uint4 b = br[q][nt];
                #pragma unroll
                for (int mt = 0; mt < 2; mt++) {
                    const unsigned ah[4] = {ah4[mt].x, ah4[mt].y, ah4[mt].z, ah4[mt].w};
                    const unsigned al[4] = {al4[mt].x, al4[mt].y, al4[mt].z, al4[mt].w};
                    mma_bf16(chh[mt][nt], ah, b.x, b.y);   // hi*hi
                    mma_bf16(cor[mt][nt], ah, b.z, b.w);   // hi*lo
                    mma_bf16(cor[mt][nt], al, b.x, b.y);   // lo*hi
                }
            }
            if (ks + 4 < 16) {
                br[q][0] = Xq[((ks + 4) * 128 + n0) * 4 + tig];
                br[q][1] = Xq[((ks + 4) * 128 + n1) * 4 + tig];
            }
        }
    }

    // ---- epilogue: write partials (standard m16n8 C mapping) ----
    float* pb = part + (size_t)split * BATCH * DIM;
    #pragma unroll
    for (int mt = 0; mt < 2; mt++) {
        const int r = m0 + mt * 16 + gid;
        #pragma unroll
        for (int nt = 0; nt < 2; nt++) {
            const int n = nb + nt * 8 + 2 * tig;
            pb[r * DIM + n]           = chh[mt][nt][0] + cor[mt][nt][0];
            pb[r * DIM + n + 1]       = chh[mt][nt][1] + cor[mt][nt][1];
            pb[(r + 8) * DIM + n]     = chh[mt][nt][2] + cor[mt][nt][2];
            pb[(r + 8) * DIM + n + 1] = chh[mt][nt][3] + cor[mt][nt][3];
        }
    }
}

// ---------------------------------------------------------------------------
// Kernel 3: reduce 4 K-split partials.
//  MODE 0: re-split to Xb fragment layout (feeds next GEMM).
//  MODE 1: fused selu + row L2-normalize -> final output.
// ---------------------------------------------------------------------------
template <int MODE>
__global__ void __launch_bounds__(128) reduce_kernel(
    const float* __restrict__ part,
    void* __restrict__ outv)
{
    const int m = blockIdx.x;
    const int n = threadIdx.x;

    float s = 0.f;
    #pragma unroll
    for (int sp = 0; sp < 4; sp++)
        s += part[((size_t)sp * BATCH + m) * DIM + n];

    if (MODE == 0) {
        xb_write((unsigned*)outv, m, n, s);
    } else {
        const float SELU_SCALE = 1.0507009873554804934f;
        const float SELU_ALPHA = 1.6732632423543772848f;
        const float sv = (s > 0.f) ? SELU_SCALE * s
                                   : SELU_SCALE * SELU_ALPHA * (expf(s) - 1.f);
        float sq = sv * sv;
        #pragma unroll
        for (int o = 16; o; o >>= 1) sq += __shfl_xor_sync(0xFFFFFFFFu, sq, o);
        __shared__ float ws[4];
        if ((n & 31) == 0) ws[n >> 5] = sq;
        __syncthreads();
        const float tot = ws[0] + ws[1] + ws[2] + ws[3];
        ((float*)outv)[m * DIM + n] = sv * rsqrtf(tot);
    }
}

// ---------------------------------------------------------------------------
// Launch: gather(->Xb) -> TC-GEMM(A) -> reduce(->Xb) -> TC-GEMM(D)
//         -> reduce+selu+norm
// (attention/entmax path is analytically identity on g: scores constant
//  along L, entmax of a constant is uniform, sum(p)*g = g)
// ---------------------------------------------------------------------------
extern "C" void kernel_launch(void* const* d_in, const int* in_sizes, int n_in,
                              void* d_out, int out_size)
{
    const float* emb   = (const float*)d_in[0];  // [500000, 128]
    const void*  items = d_in[1];                // [1024, 200] int64/int32
    const float* Amat  = (const float*)d_in[2];  // [1024, 1024]
    const float* Dmat  = (const float*)d_in[3];  // [1024, 1024]
    float* out = (float*)d_out;                  // [1024, 128]

    unsigned *xb0, *xb1;
    float *part;
    cudaGetSymbolAddress((void**)&xb0, xb0_buf);
    cudaGetSymbolAddress((void**)&xb1, xb1_buf);
    cudaGetSymbolAddress((void**)&part, part_buf);

    gather_sum_kernel<<<BATCH, 256>>>(emb, items, xb0);

    gemm_tc_kernel<<<128, 256>>>(Amat, (const uint4*)xb0, part);   // A@g
    reduce_kernel<0><<<BATCH, DIM>>>(part, xb1);                   // -> Xb(ag)

    gemm_tc_kernel<<<128, 256>>>(Dmat, (const uint4*)xb1, part);   // D@ag
    reduce_kernel<1><<<BATCH, DIM>>>(part, out);                   // selu+norm
}

// round 16
// speedup vs baseline: 1.3359x; 1.0617x over previous
#include <cuda_runtime.h>
#include <cuda_bf16.h>
#include <cstdint>

#define BATCH 1024
#define SEQL  200
#define DIM   128

// Scratch (allocation-free rule: __device__ globals)
// Xb layout: [64 ksteps][128 n][4 tig] uint4 = {b0hi, b1hi, b0lo, b1lo}
// (bf16x2 each). kstep covers k = ks*16 .. ks*16+15; within a fragment:
//   b0 = rows 2*tig,2*tig+1; b1 = rows 2*tig+8,2*tig+9; col = gid.
__device__ unsigned xb0_buf[64 * 128 * 16];        // g   (512 KB)
__device__ unsigned xb1_buf[64 * 128 * 16];        // ag  (512 KB)
__device__ float    part_buf[4 * BATCH * DIM];     // 4 K-split partials (2 MB)

// ---------------------------------------------------------------------------
// bf16 split helpers (Ootomo 3-product scheme: hh + hl + lh)
// ---------------------------------------------------------------------------
__device__ __forceinline__ void bf16_split(float v, unsigned short& h, unsigned short& l) {
    __nv_bfloat16 hb = __float2bfloat16(v);
    __nv_bfloat16 lb = __float2bfloat16(v - __bfloat162float(hb));
    h = *(unsigned short*)&hb;
    l = *(unsigned short*)&lb;
}
// split a float2 (k-even, k-odd) into packed hi-uint and lo-uint
__device__ __forceinline__ void split2(float2 f, unsigned& h, unsigned& l) {
    unsigned short h0, l0, h1, l1;
    bf16_split(f.x, h0, l0);
    bf16_split(f.y, h1, l1);
    h = (unsigned)h0 | ((unsigned)h1 << 16);
    l = (unsigned)l0 | ((unsigned)l1 << 16);
}
__device__ __forceinline__ void mma_bf16(float c[4],
                                         const unsigned a[4],
                                         unsigned b0, unsigned b1) {
    asm volatile(
        "mma.sync.aligned.m16n8k16.row.col.f32.bf16.bf16.f32 "
        "{%0,%1,%2,%3}, {%4,%5,%6,%7}, {%8,%9}, {%0,%1,%2,%3};"
        : "+f"(c[0]), "+f"(c[1]), "+f"(c[2]), "+f"(c[3])
        : "r"(a[0]), "r"(a[1]), "r"(a[2]), "r"(a[3]), "r"(b0), "r"(b1));
}

// Write one value of X[k][n] into the Xb fragment layout (hi/lo bf16).
__device__ __forceinline__ void xb_write(unsigned* xb, int k, int n, float v) {
    const int ks  = k >> 4;
    const int r   = k & 15;
    const int reg = (r >= 8) ? 1 : 0;
    const int rr  = r & 7;
    const int tig = rr >> 1;
    const int e   = rr & 1;
    unsigned short h, l; bf16_split(v, h, l);
    unsigned short* s = (unsigned short*)(xb + (((ks * 128 + n) * 4 + tig) << 2));
    s[reg * 2 + e]     = h;   // uint4.x/.y
    s[4 + reg * 2 + e] = l;   // uint4.z/.w
}

// ---------------------------------------------------------------------------
// Kernel 1: g[b] = sum_l item_embedding[items[b,l]]; writes Xb frag layout.
// (DRAM-saturated random gather: ~86 MB compulsory @ ~3.9-4 TB/s.)
// ---------------------------------------------------------------------------
__global__ void __launch_bounds__(256) gather_sum_kernel(
    const float* __restrict__ emb,
    const void* __restrict__ items_raw,
    unsigned* __restrict__ xb)
{
    const int b    = blockIdx.x;
    const int t    = threadIdx.x;
    const int w    = t >> 5;
    const int lane = t & 31;

    __shared__ int sidx[SEQL];
    __shared__ int mode64;
    __shared__ float4 spart[8][32];

    if (t == 0) {
        // int64 storage => odd int32 words of first 16 elements are all zero
        const int* p = (const int*)items_raw;
        int ok = 1;
        #pragma unroll
        for (int i = 0; i < 16; i++) ok &= (p[2 * i + 1] == 0);
        mode64 = ok;
    }
    __syncthreads();

    if (t < SEQL) {
        if (mode64) sidx[t] = (int)((const long long*)items_raw)[(long long)b * SEQL + t];
        else        sidx[t] = ((const int*)items_raw)[b * SEQL + t];
    }
    __syncthreads();

    float4 acc[5], v[5];
    #pragma unroll
    for (int j = 0; j < 5; j++) acc[j] = make_float4(0.f, 0.f, 0.f, 0.f);

    #pragma unroll
    for (int j = 0; j < 5; j++)
        v[j] = *(const float4*)&emb[(size_t)sidx[w + 8 * j] * DIM + lane * 4];

    #pragma unroll
    for (int s = 0; s < 5; s++) {
        float4 nv[5];
        if (s < 4) {
            #pragma unroll
            for (int j = 0; j < 5; j++)
                nv[j] = *(const float4*)&emb[(size_t)sidx[w + 8 * (5 * (s + 1) + j)] * DIM + lane * 4];
        }
        #pragma unroll
        for (int j = 0; j < 5; j++) {
            acc[j].x += v[j].x; acc[j].y += v[j].y;
            acc[j].z += v[j].z; acc[j].w += v[j].w;
        }
        if (s < 4) {
            #pragma unroll
            for (int j = 0; j < 5; j++) v[j] = nv[j];
        }
    }

    float4 s4;
    s4.x = ((acc[0].x + acc[1].x) + (acc[2].x + acc[3].x)) + acc[4].x;
    s4.y = ((acc[0].y + acc[1].y) + (acc[2].y + acc[3].y)) + acc[4].y;
    s4.z = ((acc[0].z + acc[1].z) + (acc[2].z + acc[3].z)) + acc[4].z;
    s4.w = ((acc[0].w + acc[1].w) + (acc[2].w + acc[3].w)) + acc[4].w;

    spart[w][lane] = s4;
    __syncthreads();
    if (w < 4) {
        float4 a = spart[w][lane], c = spart[w + 4][lane];
        a.x += c.x; a.y += c.y; a.z += c.z; a.w += c.w;
        spart[w][lane] = a;
    }
    __syncthreads();
    if (w < 2) {
        float4 a = spart[w][lane], c = spart[w + 2][lane];
        a.x += c.x; a.y += c.y; a.z += c.z; a.w += c.w;
        spart[w][lane] = a;
    }
    __syncthreads();
    if (w == 0) {
        float4 a = spart[0][lane], c = spart[1][lane];
        a.x += c.x; a.y += c.y; a.z += c.z; a.w += c.w;
        const float av[4] = {a.x, a.y, a.z, a.w};
        #pragma unroll
        for (int j = 0; j < 4; j++)
            xb_write(xb, b, lane * 4 + j, av[j]);
    }
}

// ---------------------------------------------------------------------------
// Kernel 2: tensor-core 3xBF16 (Ootomo) GEMM partial (BM=32, K-split=4):
//   part[split][m0:m0+32][:] (+)= A[m0:m0+32, k0:k0+256] @ X[k0:k0+256, :]
// grid = 128 blocks (32 m-groups x 4 K-splits) = ONE wave, 512 threads
// (16 warps = 4/SMSP for latency hiding).
//
// Warp (wk = warp>>3, wn = warp&7): n-slice wn*16, kstep half wk
// (warps 0-7 do ksteps 0-7 of the split, warps 8-15 do ksteps 8-15).
// End: wk=1 warps dump partials to smem (aliasing dead sAraw); wk=0 adds.
//
// Prologue processes the 32x256 A slice in TWO 128-col halves through a
// 16 KB fp32 staging buffer (smem: 16+16+16 = 48 KB static):
//   LDG h0 -> STS -> sync -> [LDG h1 into regs | convert ks 0-7] -> sync
//   -> STS h1 -> sync -> convert ks 8-15 -> sync
// Fragment semantics identical to the R13-verified layout.
// ---------------------------------------------------------------------------
__global__ void __launch_bounds__(512) gemm_tc_kernel(
    const float* __restrict__ A,
    const uint4* __restrict__ Xb,    // [64 ksteps][128 n][4 tig]
    float* __restrict__ part)
{
    const int mg    = blockIdx.x >> 2;   // 0..31
    const int split = blockIdx.x & 3;    // 0..3
    const int m0 = mg * 32;
    const int k0 = split * 256;

    __shared__ __align__(16) float    sAraw[32][128];       // 16 KB (one half)
    __shared__ __align__(16) unsigned sAfh[16][2][32][4];   // 16 KB
    __shared__ __align__(16) unsigned sAfl[16][2][32][4];   // 16 KB

    // cross-k-half reduction buffer aliases sAraw (dead after prologue)
    float* redf = &sAraw[0][0];   // needs 8*2*2*32*4 = 4096 floats = 16 KB

    const int tid = threadIdx.x;

    // one half = 1024 float4 -> 2 per thread (512 threads)
    float4 ld[2];

    // ---- half 0: LDG + STS ----
    #pragma unroll
    for (int j = 0; j < 2; j++) {
        const int u = tid + 512 * j;
        ld[j] = *(const float4*)&A[(size_t)(m0 + (u >> 5)) * 1024 + k0 + (u & 31) * 4];
    }
    #pragma unroll
    for (int j = 0; j < 2; j++) {
        const int u = tid + 512 * j;
        *(float4*)&sAraw[u >> 5][(u & 31) * 4] = ld[j];
    }
    __syncthreads();

    // ---- LDG half 1 into regs (latency buried under convert of half 0) ----
    #pragma unroll
    for (int j = 0; j < 2; j++) {
        const int u = tid + 512 * j;
        ld[j] = *(const float4*)&A[(size_t)(m0 + (u >> 5)) * 1024 + k0 + 128 + (u & 31) * 4];
    }

    // ---- convert half 0: ks 0..7 (512 tuples, 1 per thread) ----
    {
        const int idx  = tid;                // 0..511
        const int lane = idx & 31;
        const int mt   = (idx >> 5) & 1;
        const int ksl  = idx >> 6;           // 0..7
        const int gid8 = lane >> 2;
        const int tig  = lane & 3;
        const int r0   = mt * 16 + gid8;
        const int r1   = r0 + 8;
        const int kb2  = ksl * 16 + 2 * tig;

        const float2 f00 = *(const float2*)&sAraw[r0][kb2];
        const float2 f10 = *(const float2*)&sAraw[r1][kb2];
        const float2 f01 = *(const float2*)&sAraw[r0][kb2 + 8];
        const float2 f11 = *(const float2*)&sAraw[r1][kb2 + 8];

        uint4 hv, lv;
        split2(f00, hv.x, lv.x);   // reg0: row lo, k lo
        split2(f10, hv.y, lv.y);   // reg1: row hi, k lo
        split2(f01, hv.z, lv.z);   // reg2: row lo, k hi
        split2(f11, hv.w, lv.w);   // reg3: row hi, k hi
        *(uint4*)&sAfh[ksl][mt][lane][0] = hv;
        *(uint4*)&sAfl[ksl][mt][lane][0] = lv;
    }
    __syncthreads();

    // ---- half 1: STS ----
    #pragma unroll
    for (int j = 0; j < 2; j++) {
        const int u = tid + 512 * j;
        *(float4*)&sAraw[u >> 5][(u & 31) * 4] = ld[j];
    }
    __syncthreads();

    // ---- convert half 1: ks 8..15 ----
    {
        const int idx  = tid;
        const int lane = idx & 31;
        const int mt   = (idx >> 5) & 1;
        const int ksl  = idx >> 6;           // 0..7
        const int gid8 = lane >> 2;
        const int tig  = lane & 3;
        const int r0   = mt * 16 + gid8;
        const int r1   = r0 + 8;
        const int kb2  = ksl * 16 + 2 * tig;

        const float2 f00 = *(const float2*)&sAraw[r0][kb2];
        const float2 f10 = *(const float2*)&sAraw[r1][kb2];
        const float2 f01 = *(const float2*)&sAraw[r0][kb2 + 8];
        const float2 f11 = *(const float2*)&sAraw[r1][kb2 + 8];

        uint4 hv, lv;
        split2(f00, hv.x, lv.x);
        split2(f10, hv.y, lv.y);
        split2(f01, hv.z, lv.z);
        split2(f11, hv.w, lv.w);
        *(uint4*)&sAfh[8 + ksl][mt][lane][0] = hv;
        *(uint4*)&sAfl[8 + ksl][mt][lane][0] = lv;
    }
    __syncthreads();

    const int lane = tid & 31;
    const int warp = tid >> 5;   // 0..15
    const int wk   = warp >> 3;  // kstep half: 0 -> ks 0..7, 1 -> ks 8..15
    const int wn   = warp & 7;   // n-slice
    const int gid  = lane >> 2;
    const int tig  = lane & 3;
    const int nb   = wn * 16;
    const int ksbase = wk * 8;

    float chh[2][2][4], cor[2][2][4];
    #pragma unroll
    for (int mt = 0; mt < 2; mt++)
        #pragma unroll
        for (int nt = 0; nt < 2; nt++)
            #pragma unroll
            for (int i = 0; i < 4; i++) { chh[mt][nt][i] = 0.f; cor[mt][nt][i] = 0.f; }

    const uint4* Xq = Xb + (size_t)(split * 16) * 128 * 4;
    const int n0 = nb + gid;
    const int n1 = nb + 8 + gid;

    // ring prefetch: 4 ksteps deep (of this warp's 8)
    uint4 br[4][2];
    #pragma unroll
    for (int q = 0; q < 4; q++) {
        br[q][0] = Xq[((ksbase + q) * 128 + n0) * 4 + tig];
        br[q][1] = Xq[((ksbase + q) * 128 + n1) * 4 + tig];
    }

    #pragma unroll
    for (int ksb = 0; ksb < 8; ksb += 4) {
        #pragma unroll
        for (int q = 0; q < 4; q++) {
            const int ksl = ksb + q;              // 0..7 local
            const int ks  = ksbase + ksl;         // smem kstep index
            uint4 ah4[2], al4[2];
            #pragma unroll
            for (int mt = 0; mt < 2; mt++) {
                ah4[mt] = *(const uint4*)&sAfh[ks][mt][lane][0];
                al4[mt] = *(const uint4*)&sAfl[ks][mt][lane][0];
            }
            #pragma unroll
            for (int nt = 0; nt < 2; nt++) {
                const uint4 b = br[q][nt];
                #pragma unroll
                for (int mt = 0; mt < 2; mt++) {
                    const unsigned ah[4] = {ah4[mt].x, ah4[mt].y, ah4[mt].z, ah4[mt].w};
                    const unsigned al[4] = {al4[mt].x, al4[mt].y, al4[mt].z, al4[mt].w};
                    mma_bf16(chh[mt][nt], ah, b.x, b.y);   // hi*hi
                    mma_bf16(cor[mt][nt], ah, b.z, b.w);   // hi*lo
                    mma_bf16(cor[mt][nt], al, b.x, b.y);   // lo*hi
                }
            }
            if (ksl + 4 < 8) {
                br[q][0] = Xq[((ks + 4) * 128 + n0) * 4 + tig];
                br[q][1] = Xq[((ks + 4) * 128 + n1) * 4 + tig];
            }
        }
    }

    // ---- cross-k-half reduction (redf aliases sAraw) ----
    __syncthreads();   // all sAraw prologue traffic long done; barrier for alias safety
    if (wk == 1) {
        #pragma unroll
        for (int mt = 0; mt < 2; mt++)
            #pragma unroll
            for (int nt = 0; nt < 2; nt++)
                #pragma unroll
                for (int i = 0; i < 4; i++)
                    redf[((((wn * 2 + mt) * 2 + nt) * 32) + lane) * 4 + i] =
                        chh[mt][nt][i] + cor[mt][nt][i];
    }
    __syncthreads();

    if (wk == 0) {
        float* pb = part + (size_t)split * BATCH * DIM;
        #pragma unroll
        for (int mt = 0; mt < 2; mt++) {
            const int r = m0 + mt * 16 + gid;
            #pragma unroll
            for (int nt = 0; nt < 2; nt++) {
                const int n = nb + nt * 8 + 2 * tig;
                const float* rf = &redf[((((wn * 2 + mt) * 2 + nt) * 32) + lane) * 4];
                pb[r * DIM + n]           = chh[mt][nt][0] + cor[mt][nt][0] + rf[0];
                pb[r * DIM + n + 1]       = chh[mt][nt][1] + cor[mt][nt][1] + rf[1];
                pb[(r + 8) * DIM + n]     = chh[mt][nt][2] + cor[mt][nt][2] + rf[2];
                pb[(r + 8) * DIM + n + 1] = chh[mt][nt][3] + cor[mt][nt][3] + rf[3];
            }
        }
    }
}

// ---------------------------------------------------------------------------
// Kernel 3: reduce 4 K-split partials.
//  MODE 0: re-split to Xb fragment layout (feeds next GEMM).
//  MODE 1: fused selu + row L2-normalize -> final output.
// ---------------------------------------------------------------------------
template <int MODE>
__global__ void __launch_bounds__(128) reduce_kernel(
    const float* __restrict__ part,
    void* __restrict__ outv)
{
    const int m = blockIdx.x;
    const int n = threadIdx.x;

    float s = 0.f;
    #pragma unroll
    for (int sp = 0; sp < 4; sp++)
        s += part[((size_t)sp * BATCH + m) * DIM + n];

    if (MODE == 0) {
        xb_write((unsigned*)outv, m, n, s);
    } else {
        const float SELU_SCALE = 1.0507009873554804934f;
        const float SELU_ALPHA = 1.6732632423543772848f;
        const float sv = (s > 0.f) ? SELU_SCALE * s
                                   : SELU_SCALE * SELU_ALPHA * (expf(s) - 1.f);
        float sq = sv * sv;
        #pragma unroll
        for (int o = 16; o; o >>= 1) sq += __shfl_xor_sync(0xFFFFFFFFu, sq, o);
        __shared__ float ws[4];
        if ((n & 31) == 0) ws[n >> 5] = sq;
        __syncthreads();
        const float tot = ws[0] + ws[1] + ws[2] + ws[3];
        ((float*)outv)[m * DIM + n] = sv * rsqrtf(tot);
    }
}

// ---------------------------------------------------------------------------
// Launch: gather(->Xb) -> TC-GEMM(A) -> reduce(->Xb) -> TC-GEMM(D)
//         -> reduce+selu+norm
// (attention/entmax path is analytically identity on g: scores constant
//  along L, entmax of a constant is uniform, sum(p)*g = g)
// ---------------------------------------------------------------------------
extern "C" void kernel_launch(void* const* d_in, const int* in_sizes, int n_in,
                              void* d_out, int out_size)
{
    const float* emb   = (const float*)d_in[0];  // [500000, 128]
    const void*  items = d_in[1];                // [1024, 200] int64/int32
    const float* Amat  = (const float*)d_in[2];  // [1024, 1024]
    const float* Dmat  = (const float*)d_in[3];  // [1024, 1024]
    float* out = (float*)d_out;                  // [1024, 128]

    unsigned *xb0, *xb1;
    float *part;
    cudaGetSymbolAddress((void**)&xb0, xb0_buf);
    cudaGetSymbolAddress((void**)&xb1, xb1_buf);
    cudaGetSymbolAddress((void**)&part, part_buf);

    gather_sum_kernel<<<BATCH, 256>>>(emb, items, xb0);

    gemm_tc_kernel<<<128, 512>>>(Amat, (const uint4*)xb0, part);   // A@g
    reduce_kernel<0><<<BATCH, DIM>>>(part, xb1);                   // -> Xb(ag)

    gemm_tc_kernel<<<128, 512>>>(Dmat, (const uint4*)xb1, part);   // D@ag
    reduce_kernel<1><<<BATCH, DIM>>>(part, out);                   // selu+norm
}